// round 4
// baseline (speedup 1.0000x reference)
#include <cuda_runtime.h>
#include <math.h>

#define Bsz 32
#define Ssz 2048
#define Hsz 1024
#define ECH 64                  // e-chunks for u partial sums (16 e's each)
#define WPC 8                   // warps per CTA in pass1
#define CPB 16                  // CTAs per batch element in pass1
#define SPLITS (WPC*CPB)        // 128 warp-splits per batch row
#define RPW (Ssz/SPLITS)        // 16 rows per warp

// Scratch (device globals: allocation-free per harness rules)
__device__ float  g_u_part[ECH][Hsz];
__device__ float  g_u[Hsz];
__device__ float  g_scores[Bsz*Ssz];
__device__ float  g_part_m[Bsz*SPLITS];
__device__ float  g_part_l[Bsz*SPLITS];
__device__ float4 g_part_acc[(size_t)Bsz*SPLITS*(Hsz/4)];

// K0: u_part[c][h] = sum over a 16-wide e-chunk of v[e] * W[e, H+h].
// grid (8, 64), block 128 -> 512 CTAs, fully unrolled 16-deep e-loop (MLP=16).
__global__ void k_u(const float* __restrict__ W, const float* __restrict__ v) {
    int h  = blockIdx.x * blockDim.x + threadIdx.x;   // 0..1023
    int e0 = blockIdx.y * (Hsz/ECH);                  // 16 e's per chunk
    float s = 0.f;
    #pragma unroll
    for (int e = 0; e < Hsz/ECH; ++e)
        s = fmaf(__ldg(v + e0 + e),
                 __ldg(W + (size_t)(e0 + e)*(2*Hsz) + Hsz + h), s);
    g_u_part[blockIdx.y][h] = s;
}

// K0b: fold the 64 partials (L2-resident, 256 KB) into g_u[1024].
__global__ void k_u_reduce() {
    int h = blockIdx.x * blockDim.x + threadIdx.x;
    float s = 0.f;
    #pragma unroll
    for (int c = 0; c < ECH; ++c) s += g_u_part[c][h];
    g_u[h] = s;
}

// K1: single pass over encoder_outputs. Each warp owns RPW sequence rows of
// one batch element, processes 2 rows per iteration (16 front-batched
// LDG.128 -> MLP_p1=16), maintains online-softmax (m, l, acc[32 regs/lane]).
__global__ void __launch_bounds__(256, 2) k_pass1(const float* __restrict__ enc) {
    __shared__ float4 su[Hsz/4];
    // u into smem: one float4 per thread (4 KB total)
    su[threadIdx.x] = ((const float4*)g_u)[threadIdx.x];
    __syncthreads();

    int b    = blockIdx.x / CPB;
    int warp = (blockIdx.x % CPB) * WPC + (threadIdx.x >> 5);
    int lane = threadIdx.x & 31;
    int s0   = warp * RPW;

    const float4* base = (const float4*)enc + (size_t)(b*Ssz + s0) * (Hsz/4);

    float4 uv[8];
    #pragma unroll
    for (int j = 0; j < 8; ++j) uv[j] = su[j*32 + lane];

    float acc[32];
    #pragma unroll
    for (int i = 0; i < 32; ++i) acc[i] = 0.f;
    float m = -INFINITY, l = 0.f;

    for (int r = 0; r < RPW; r += 2) {
        const float4* rowA = base + (size_t)r * (Hsz/4);
        const float4* rowB = rowA + (Hsz/4);
        float4 xa[8], xb[8];
        #pragma unroll
        for (int j = 0; j < 8; ++j) xa[j] = rowA[j*32 + lane];
        #pragma unroll
        for (int j = 0; j < 8; ++j) xb[j] = rowB[j*32 + lane];

        float da = 0.f, db = 0.f;
        #pragma unroll
        for (int j = 0; j < 8; ++j) {
            da = fmaf(xa[j].x, uv[j].x, da);
            da = fmaf(xa[j].y, uv[j].y, da);
            da = fmaf(xa[j].z, uv[j].z, da);
            da = fmaf(xa[j].w, uv[j].w, da);
            db = fmaf(xb[j].x, uv[j].x, db);
            db = fmaf(xb[j].y, uv[j].y, db);
            db = fmaf(xb[j].z, uv[j].z, db);
            db = fmaf(xb[j].w, uv[j].w, db);
        }
        #pragma unroll
        for (int off = 16; off > 0; off >>= 1) {
            da += __shfl_xor_sync(0xffffffffu, da, off);
            db += __shfl_xor_sync(0xffffffffu, db, off);
        }

        if (lane == 0) {
            g_scores[b*Ssz + s0 + r]     = da;
            g_scores[b*Ssz + s0 + r + 1] = db;
        }

        // online softmax, row A
        if (da > m) {
            float alpha = __expf(m - da);
            l = fmaf(l, alpha, 1.f);
            #pragma unroll
            for (int j = 0; j < 8; ++j) {
                acc[4*j+0] = fmaf(acc[4*j+0], alpha, xa[j].x);
                acc[4*j+1] = fmaf(acc[4*j+1], alpha, xa[j].y);
                acc[4*j+2] = fmaf(acc[4*j+2], alpha, xa[j].z);
                acc[4*j+3] = fmaf(acc[4*j+3], alpha, xa[j].w);
            }
            m = da;
        } else {
            float p = __expf(da - m);
            l += p;
            #pragma unroll
            for (int j = 0; j < 8; ++j) {
                acc[4*j+0] = fmaf(p, xa[j].x, acc[4*j+0]);
                acc[4*j+1] = fmaf(p, xa[j].y, acc[4*j+1]);
                acc[4*j+2] = fmaf(p, xa[j].z, acc[4*j+2]);
                acc[4*j+3] = fmaf(p, xa[j].w, acc[4*j+3]);
            }
        }
        // online softmax, row B
        if (db > m) {
            float alpha = __expf(m - db);
            l = fmaf(l, alpha, 1.f);
            #pragma unroll
            for (int j = 0; j < 8; ++j) {
                acc[4*j+0] = fmaf(acc[4*j+0], alpha, xb[j].x);
                acc[4*j+1] = fmaf(acc[4*j+1], alpha, xb[j].y);
                acc[4*j+2] = fmaf(acc[4*j+2], alpha, xb[j].z);
                acc[4*j+3] = fmaf(acc[4*j+3], alpha, xb[j].w);
            }
            m = db;
        } else {
            float p = __expf(db - m);
            l += p;
            #pragma unroll
            for (int j = 0; j < 8; ++j) {
                acc[4*j+0] = fmaf(p, xb[j].x, acc[4*j+0]);
                acc[4*j+1] = fmaf(p, xb[j].y, acc[4*j+1]);
                acc[4*j+2] = fmaf(p, xb[j].z, acc[4*j+2]);
                acc[4*j+3] = fmaf(p, xb[j].w, acc[4*j+3]);
            }
        }
    }

    int pidx = b*SPLITS + warp;
    if (lane == 0) { g_part_m[pidx] = m; g_part_l[pidx] = l; }
    #pragma unroll
    for (int j = 0; j < 8; ++j)
        g_part_acc[(size_t)pidx*(Hsz/4) + j*32 + lane] =
            make_float4(acc[4*j], acc[4*j+1], acc[4*j+2], acc[4*j+3]);
}

// K2: per batch element, merge SPLITS partials -> context (out[0:B*H]) and
// attention weights (out[B*H : B*H + B*S]).
__global__ void k_combine(float* __restrict__ out) {
    int b = blockIdx.x;
    int t = threadIdx.x;  // 256 threads; t indexes one float4 of H

    float M = -INFINITY;
    #pragma unroll 8
    for (int k = 0; k < SPLITS; ++k)
        M = fmaxf(M, g_part_m[b*SPLITS + k]);

    float L = 0.f;
    float4 c = make_float4(0.f, 0.f, 0.f, 0.f);
    #pragma unroll 4
    for (int k = 0; k < SPLITS; ++k) {
        float wk = __expf(g_part_m[b*SPLITS + k] - M);
        L = fmaf(wk, g_part_l[b*SPLITS + k], L);
        float4 a = g_part_acc[(size_t)(b*SPLITS + k)*(Hsz/4) + t];
        c.x = fmaf(wk, a.x, c.x);
        c.y = fmaf(wk, a.y, c.y);
        c.z = fmaf(wk, a.z, c.z);
        c.w = fmaf(wk, a.w, c.w);
    }
    float inv = 1.f / L;
    c.x *= inv; c.y *= inv; c.z *= inv; c.w *= inv;
    ((float4*)out)[b*(Hsz/4) + t] = c;

    // attention weights: softmax(scores) with the exact same M, L
    float* wout = out + Bsz*Hsz + b*Ssz;
    #pragma unroll
    for (int s = t; s < Ssz; s += 256)
        wout[s] = __expf(g_scores[b*Ssz + s] - M) * inv;
}

extern "C" void kernel_launch(void* const* d_in, const int* in_sizes, int n_in,
                              void* d_out, int out_size) {
    // metadata order: hidden_state, encoder_outputs, W, b, v, batch_size, seq_len
    const float* enc = (const float*)d_in[1];
    const float* W   = (const float*)d_in[2];
    const float* v   = (const float*)d_in[4];
    float* out = (float*)d_out;

    k_u<<<dim3(Hsz/128, ECH), 128>>>(W, v);
    k_u_reduce<<<Hsz/128, 128>>>();
    k_pass1<<<Bsz*CPB, 256>>>(enc);
    k_combine<<<Bsz, 256>>>(out);
}

// round 5
// speedup vs baseline: 1.5394x; 1.5394x over previous
#include <cuda_runtime.h>
#include <math.h>

#define Bsz 32
#define Ssz 2048
#define Hsz 1024
#define ECH 64                  // e-chunks for u partial sums (16 e's each)
#define WPC 8                   // warps per CTA in pass1
#define CPB 16                  // CTAs per batch element in pass1
#define SPLITS CPB              // one merged partial per CTA (CTA-level merge)
#define RPW (Ssz/(WPC*CPB))     // 16 rows per warp

// Scratch (device globals: allocation-free per harness rules)
__device__ float  g_u_part[ECH][Hsz];
__device__ float  g_u[Hsz];
__device__ float  g_scores[Bsz*Ssz];
__device__ float  g_part_m[Bsz*SPLITS];
__device__ float  g_part_l[Bsz*SPLITS];
__device__ float4 g_part_acc[(size_t)Bsz*SPLITS*(Hsz/4)];

// K0: u_part[c][h] = sum over a 16-wide e-chunk of v[e] * W[e, H+h].
__global__ void k_u(const float* __restrict__ W, const float* __restrict__ v) {
    int h  = blockIdx.x * blockDim.x + threadIdx.x;   // 0..1023
    int e0 = blockIdx.y * (Hsz/ECH);                  // 16 e's per chunk
    float s = 0.f;
    #pragma unroll
    for (int e = 0; e < Hsz/ECH; ++e)
        s = fmaf(__ldg(v + e0 + e),
                 __ldg(W + (size_t)(e0 + e)*(2*Hsz) + Hsz + h), s);
    g_u_part[blockIdx.y][h] = s;
}

// K0b: fold the 64 partials (L2-resident, 256 KB) into g_u[1024].
__global__ void k_u_reduce() {
    int h = blockIdx.x * blockDim.x + threadIdx.x;
    float s = 0.f;
    #pragma unroll
    for (int c = 0; c < ECH; ++c) s += g_u_part[c][h];
    g_u[h] = s;
}

// K1: single pass over encoder_outputs. Each warp owns RPW sequence rows of
// one batch element, processes 2 rows per iteration (16 front-batched
// LDG.128), maintains online-softmax (m, l, acc[32 regs/lane]). The 8 warps
// of a CTA then merge their partials in smem, so only ONE partial per CTA
// hits global memory (2 MB total instead of 16 MB).
__global__ void __launch_bounds__(256, 2) k_pass1(const float* __restrict__ enc) {
    __shared__ float4 su[Hsz/4];                 // 4 KB
    __shared__ float4 s_acc[WPC][Hsz/4];         // 32 KB
    __shared__ float  s_m[WPC], s_l[WPC];

    su[threadIdx.x] = ((const float4*)g_u)[threadIdx.x];
    __syncthreads();

    int b    = blockIdx.x / CPB;
    int cw   = threadIdx.x >> 5;                 // warp within CTA
    int warp = (blockIdx.x % CPB) * WPC + cw;    // global split id
    int lane = threadIdx.x & 31;
    int s0   = warp * RPW;

    const float4* base = (const float4*)enc + (size_t)(b*Ssz + s0) * (Hsz/4);

    float4 uv[8];
    #pragma unroll
    for (int j = 0; j < 8; ++j) uv[j] = su[j*32 + lane];

    float acc[32];
    #pragma unroll
    for (int i = 0; i < 32; ++i) acc[i] = 0.f;
    float m = -INFINITY, l = 0.f;

    for (int r = 0; r < RPW; r += 2) {
        const float4* rowA = base + (size_t)r * (Hsz/4);
        const float4* rowB = rowA + (Hsz/4);
        float4 xa[8], xb[8];
        #pragma unroll
        for (int j = 0; j < 8; ++j) xa[j] = rowA[j*32 + lane];
        #pragma unroll
        for (int j = 0; j < 8; ++j) xb[j] = rowB[j*32 + lane];

        float da = 0.f, db = 0.f;
        #pragma unroll
        for (int j = 0; j < 8; ++j) {
            da = fmaf(xa[j].x, uv[j].x, da);
            da = fmaf(xa[j].y, uv[j].y, da);
            da = fmaf(xa[j].z, uv[j].z, da);
            da = fmaf(xa[j].w, uv[j].w, da);
            db = fmaf(xb[j].x, uv[j].x, db);
            db = fmaf(xb[j].y, uv[j].y, db);
            db = fmaf(xb[j].z, uv[j].z, db);
            db = fmaf(xb[j].w, uv[j].w, db);
        }
        #pragma unroll
        for (int off = 16; off > 0; off >>= 1) {
            da += __shfl_xor_sync(0xffffffffu, da, off);
            db += __shfl_xor_sync(0xffffffffu, db, off);
        }

        if (lane == 0) {
            g_scores[b*Ssz + s0 + r]     = da;
            g_scores[b*Ssz + s0 + r + 1] = db;
        }

        // online softmax, row A
        if (da > m) {
            float alpha = __expf(m - da);
            l = fmaf(l, alpha, 1.f);
            #pragma unroll
            for (int j = 0; j < 8; ++j) {
                acc[4*j+0] = fmaf(acc[4*j+0], alpha, xa[j].x);
                acc[4*j+1] = fmaf(acc[4*j+1], alpha, xa[j].y);
                acc[4*j+2] = fmaf(acc[4*j+2], alpha, xa[j].z);
                acc[4*j+3] = fmaf(acc[4*j+3], alpha, xa[j].w);
            }
            m = da;
        } else {
            float p = __expf(da - m);
            l += p;
            #pragma unroll
            for (int j = 0; j < 8; ++j) {
                acc[4*j+0] = fmaf(p, xa[j].x, acc[4*j+0]);
                acc[4*j+1] = fmaf(p, xa[j].y, acc[4*j+1]);
                acc[4*j+2] = fmaf(p, xa[j].z, acc[4*j+2]);
                acc[4*j+3] = fmaf(p, xa[j].w, acc[4*j+3]);
            }
        }
        // online softmax, row B
        if (db > m) {
            float alpha = __expf(m - db);
            l = fmaf(l, alpha, 1.f);
            #pragma unroll
            for (int j = 0; j < 8; ++j) {
                acc[4*j+0] = fmaf(acc[4*j+0], alpha, xb[j].x);
                acc[4*j+1] = fmaf(acc[4*j+1], alpha, xb[j].y);
                acc[4*j+2] = fmaf(acc[4*j+2], alpha, xb[j].z);
                acc[4*j+3] = fmaf(acc[4*j+3], alpha, xb[j].w);
            }
            m = db;
        } else {
            float p = __expf(db - m);
            l += p;
            #pragma unroll
            for (int j = 0; j < 8; ++j) {
                acc[4*j+0] = fmaf(p, xb[j].x, acc[4*j+0]);
                acc[4*j+1] = fmaf(p, xb[j].y, acc[4*j+1]);
                acc[4*j+2] = fmaf(p, xb[j].z, acc[4*j+2]);
                acc[4*j+3] = fmaf(p, xb[j].w, acc[4*j+3]);
            }
        }
    }

    // --- CTA-level merge of the 8 warp partials (smem) ---
    #pragma unroll
    for (int j = 0; j < 8; ++j)
        s_acc[cw][j*32 + lane] =
            make_float4(acc[4*j], acc[4*j+1], acc[4*j+2], acc[4*j+3]);
    if (lane == 0) { s_m[cw] = m; s_l[cw] = l; }
    __syncthreads();

    // Each of the 256 threads merges one float4 column across the 8 warps.
    int t = threadIdx.x;
    float M = s_m[0];
    #pragma unroll
    for (int k = 1; k < WPC; ++k) M = fmaxf(M, s_m[k]);
    float L = 0.f;
    float4 c = make_float4(0.f, 0.f, 0.f, 0.f);
    #pragma unroll
    for (int k = 0; k < WPC; ++k) {
        float wk = __expf(s_m[k] - M);
        L = fmaf(wk, s_l[k], L);
        float4 a = s_acc[k][t];
        c.x = fmaf(wk, a.x, c.x);
        c.y = fmaf(wk, a.y, c.y);
        c.z = fmaf(wk, a.z, c.z);
        c.w = fmaf(wk, a.w, c.w);
    }

    int pidx = b*SPLITS + (blockIdx.x % CPB);
    g_part_acc[(size_t)pidx*(Hsz/4) + t] = c;
    if (t == 0) { g_part_m[pidx] = M; g_part_l[pidx] = L; }
}

// K2: per batch element, merge SPLITS(=16) CTA partials -> context
// (out[0:B*H]) and attention weights (out[B*H : B*H + B*S]).
__global__ void k_combine(float* __restrict__ out) {
    int b = blockIdx.x;
    int t = threadIdx.x;  // 256 threads; t indexes one float4 of H

    float M = -INFINITY;
    #pragma unroll
    for (int k = 0; k < SPLITS; ++k)
        M = fmaxf(M, g_part_m[b*SPLITS + k]);

    float L = 0.f;
    float4 c = make_float4(0.f, 0.f, 0.f, 0.f);
    #pragma unroll
    for (int k = 0; k < SPLITS; ++k) {
        float wk = __expf(g_part_m[b*SPLITS + k] - M);
        L = fmaf(wk, g_part_l[b*SPLITS + k], L);
        float4 a = g_part_acc[(size_t)(b*SPLITS + k)*(Hsz/4) + t];
        c.x = fmaf(wk, a.x, c.x);
        c.y = fmaf(wk, a.y, c.y);
        c.z = fmaf(wk, a.z, c.z);
        c.w = fmaf(wk, a.w, c.w);
    }
    float inv = 1.f / L;
    c.x *= inv; c.y *= inv; c.z *= inv; c.w *= inv;
    ((float4*)out)[b*(Hsz/4) + t] = c;

    // attention weights: softmax(scores) with the exact same M, L
    float* wout = out + Bsz*Hsz + b*Ssz;
    #pragma unroll
    for (int s = t; s < Ssz; s += 256)
        wout[s] = __expf(g_scores[b*Ssz + s] - M) * inv;
}

extern "C" void kernel_launch(void* const* d_in, const int* in_sizes, int n_in,
                              void* d_out, int out_size) {
    // metadata order: hidden_state, encoder_outputs, W, b, v, batch_size, seq_len
    const float* enc = (const float*)d_in[1];
    const float* W   = (const float*)d_in[2];
    const float* v   = (const float*)d_in[4];
    float* out = (float*)d_out;

    k_u<<<dim3(Hsz/128, ECH), 128>>>(W, v);
    k_u_reduce<<<Hsz/128, 128>>>();
    k_pass1<<<Bsz*CPB, 256>>>(enc);
    k_combine<<<Bsz, 256>>>(out);
}

// round 6
// speedup vs baseline: 1.5432x; 1.0025x over previous
#include <cuda_runtime.h>
#include <math.h>

#define Bsz 32
#define Ssz 2048
#define Hsz 1024
#define ECH 64                  // e-chunks for u partial sums (16 e's each)
#define WPC 8                   // warps per CTA in pass1
#define CPB 16                  // CTAs per batch element in pass1
#define SPLITS CPB              // one merged partial per CTA (CTA-level merge)
#define RPW (Ssz/(WPC*CPB))     // 16 rows per warp

// Scratch (device globals: allocation-free per harness rules)
__device__ float  g_u_part[ECH][Hsz];
__device__ float  g_u[Hsz];
__device__ float  g_scores[Bsz*Ssz];
__device__ float  g_part_m[Bsz*SPLITS];
__device__ float  g_part_l[Bsz*SPLITS];
__device__ float4 g_part_acc[(size_t)Bsz*SPLITS*(Hsz/4)];

// K0: u_part[c][h] = sum over a 16-wide e-chunk of v[e] * W[e, H+h].
__global__ void k_u(const float* __restrict__ W, const float* __restrict__ v) {
    int h  = blockIdx.x * blockDim.x + threadIdx.x;   // 0..1023
    int e0 = blockIdx.y * (Hsz/ECH);                  // 16 e's per chunk
    float s = 0.f;
    #pragma unroll
    for (int e = 0; e < Hsz/ECH; ++e)
        s = fmaf(__ldg(v + e0 + e),
                 __ldg(W + (size_t)(e0 + e)*(2*Hsz) + Hsz + h), s);
    g_u_part[blockIdx.y][h] = s;
}

// K0b: fold the 64 partials (L2-resident, 256 KB) into g_u[1024].
__global__ void k_u_reduce() {
    int h = blockIdx.x * blockDim.x + threadIdx.x;
    float s = 0.f;
    #pragma unroll
    for (int c = 0; c < ECH; ++c) s += g_u_part[c][h];
    g_u[h] = s;
}

// K1: single pass over encoder_outputs. Each warp owns RPW sequence rows of
// one batch element, processes 2 rows per iteration (16 front-batched
// LDG.128), maintains online-softmax (m, l, acc[32 regs/lane]). The 8 warps
// of a CTA then merge their partials in smem, so only ONE partial per CTA
// hits global memory (2 MB total instead of 16 MB).
__global__ void __launch_bounds__(256, 2) k_pass1(const float* __restrict__ enc) {
    __shared__ float4 su[Hsz/4];                 // 4 KB
    __shared__ float4 s_acc[WPC][Hsz/4];         // 32 KB
    __shared__ float  s_m[WPC], s_l[WPC];

    su[threadIdx.x] = ((const float4*)g_u)[threadIdx.x];
    __syncthreads();

    int b    = blockIdx.x / CPB;
    int cw   = threadIdx.x >> 5;                 // warp within CTA
    int warp = (blockIdx.x % CPB) * WPC + cw;    // global split id
    int lane = threadIdx.x & 31;
    int s0   = warp * RPW;

    const float4* base = (const float4*)enc + (size_t)(b*Ssz + s0) * (Hsz/4);

    float4 uv[8];
    #pragma unroll
    for (int j = 0; j < 8; ++j) uv[j] = su[j*32 + lane];

    float acc[32];
    #pragma unroll
    for (int i = 0; i < 32; ++i) acc[i] = 0.f;
    float m = -INFINITY, l = 0.f;

    for (int r = 0; r < RPW; r += 2) {
        const float4* rowA = base + (size_t)r * (Hsz/4);
        const float4* rowB = rowA + (Hsz/4);
        float4 xa[8], xb[8];
        #pragma unroll
        for (int j = 0; j < 8; ++j) xa[j] = rowA[j*32 + lane];
        #pragma unroll
        for (int j = 0; j < 8; ++j) xb[j] = rowB[j*32 + lane];

        float da = 0.f, db = 0.f;
        #pragma unroll
        for (int j = 0; j < 8; ++j) {
            da = fmaf(xa[j].x, uv[j].x, da);
            da = fmaf(xa[j].y, uv[j].y, da);
            da = fmaf(xa[j].z, uv[j].z, da);
            da = fmaf(xa[j].w, uv[j].w, da);
            db = fmaf(xb[j].x, uv[j].x, db);
            db = fmaf(xb[j].y, uv[j].y, db);
            db = fmaf(xb[j].z, uv[j].z, db);
            db = fmaf(xb[j].w, uv[j].w, db);
        }
        #pragma unroll
        for (int off = 16; off > 0; off >>= 1) {
            da += __shfl_xor_sync(0xffffffffu, da, off);
            db += __shfl_xor_sync(0xffffffffu, db, off);
        }

        if (lane == 0) {
            g_scores[b*Ssz + s0 + r]     = da;
            g_scores[b*Ssz + s0 + r + 1] = db;
        }

        // online softmax, row A
        if (da > m) {
            float alpha = __expf(m - da);
            l = fmaf(l, alpha, 1.f);
            #pragma unroll
            for (int j = 0; j < 8; ++j) {
                acc[4*j+0] = fmaf(acc[4*j+0], alpha, xa[j].x);
                acc[4*j+1] = fmaf(acc[4*j+1], alpha, xa[j].y);
                acc[4*j+2] = fmaf(acc[4*j+2], alpha, xa[j].z);
                acc[4*j+3] = fmaf(acc[4*j+3], alpha, xa[j].w);
            }
            m = da;
        } else {
            float p = __expf(da - m);
            l += p;
            #pragma unroll
            for (int j = 0; j < 8; ++j) {
                acc[4*j+0] = fmaf(p, xa[j].x, acc[4*j+0]);
                acc[4*j+1] = fmaf(p, xa[j].y, acc[4*j+1]);
                acc[4*j+2] = fmaf(p, xa[j].z, acc[4*j+2]);
                acc[4*j+3] = fmaf(p, xa[j].w, acc[4*j+3]);
            }
        }
        // online softmax, row B
        if (db > m) {
            float alpha = __expf(m - db);
            l = fmaf(l, alpha, 1.f);
            #pragma unroll
            for (int j = 0; j < 8; ++j) {
                acc[4*j+0] = fmaf(acc[4*j+0], alpha, xb[j].x);
                acc[4*j+1] = fmaf(acc[4*j+1], alpha, xb[j].y);
                acc[4*j+2] = fmaf(acc[4*j+2], alpha, xb[j].z);
                acc[4*j+3] = fmaf(acc[4*j+3], alpha, xb[j].w);
            }
            m = db;
        } else {
            float p = __expf(db - m);
            l += p;
            #pragma unroll
            for (int j = 0; j < 8; ++j) {
                acc[4*j+0] = fmaf(p, xb[j].x, acc[4*j+0]);
                acc[4*j+1] = fmaf(p, xb[j].y, acc[4*j+1]);
                acc[4*j+2] = fmaf(p, xb[j].z, acc[4*j+2]);
                acc[4*j+3] = fmaf(p, xb[j].w, acc[4*j+3]);
            }
        }
    }

    // --- CTA-level merge of the 8 warp partials (smem) ---
    #pragma unroll
    for (int j = 0; j < 8; ++j)
        s_acc[cw][j*32 + lane] =
            make_float4(acc[4*j], acc[4*j+1], acc[4*j+2], acc[4*j+3]);
    if (lane == 0) { s_m[cw] = m; s_l[cw] = l; }
    __syncthreads();

    // Each of the 256 threads merges one float4 column across the 8 warps.
    int t = threadIdx.x;
    float M = s_m[0];
    #pragma unroll
    for (int k = 1; k < WPC; ++k) M = fmaxf(M, s_m[k]);
    float L = 0.f;
    float4 c = make_float4(0.f, 0.f, 0.f, 0.f);
    #pragma unroll
    for (int k = 0; k < WPC; ++k) {
        float wk = __expf(s_m[k] - M);
        L = fmaf(wk, s_l[k], L);
        float4 a = s_acc[k][t];
        c.x = fmaf(wk, a.x, c.x);
        c.y = fmaf(wk, a.y, c.y);
        c.z = fmaf(wk, a.z, c.z);
        c.w = fmaf(wk, a.w, c.w);
    }

    int pidx = b*SPLITS + (blockIdx.x % CPB);
    g_part_acc[(size_t)pidx*(Hsz/4) + t] = c;
    if (t == 0) { g_part_m[pidx] = M; g_part_l[pidx] = L; }
}

// K2: per batch element, merge SPLITS(=16) CTA partials -> context
// (out[0:B*H]) and attention weights (out[B*H : B*H + B*S]).
__global__ void k_combine(float* __restrict__ out) {
    int b = blockIdx.x;
    int t = threadIdx.x;  // 256 threads; t indexes one float4 of H

    float M = -INFINITY;
    #pragma unroll
    for (int k = 0; k < SPLITS; ++k)
        M = fmaxf(M, g_part_m[b*SPLITS + k]);

    float L = 0.f;
    float4 c = make_float4(0.f, 0.f, 0.f, 0.f);
    #pragma unroll
    for (int k = 0; k < SPLITS; ++k) {
        float wk = __expf(g_part_m[b*SPLITS + k] - M);
        L = fmaf(wk, g_part_l[b*SPLITS + k], L);
        float4 a = g_part_acc[(size_t)(b*SPLITS + k)*(Hsz/4) + t];
        c.x = fmaf(wk, a.x, c.x);
        c.y = fmaf(wk, a.y, c.y);
        c.z = fmaf(wk, a.z, c.z);
        c.w = fmaf(wk, a.w, c.w);
    }
    float inv = 1.f / L;
    c.x *= inv; c.y *= inv; c.z *= inv; c.w *= inv;
    ((float4*)out)[b*(Hsz/4) + t] = c;

    // attention weights: softmax(scores) with the exact same M, L
    float* wout = out + Bsz*Hsz + b*Ssz;
    #pragma unroll
    for (int s = t; s < Ssz; s += 256)
        wout[s] = __expf(g_scores[b*Ssz + s] - M) * inv;
}

extern "C" void kernel_launch(void* const* d_in, const int* in_sizes, int n_in,
                              void* d_out, int out_size) {
    // metadata order: hidden_state, encoder_outputs, W, b, v, batch_size, seq_len
    const float* enc = (const float*)d_in[1];
    const float* W   = (const float*)d_in[2];
    const float* v   = (const float*)d_in[4];
    float* out = (float*)d_out;

    k_u<<<dim3(Hsz/128, ECH), 128>>>(W, v);
    k_u_reduce<<<Hsz/128, 128>>>();
    k_pass1<<<Bsz*CPB, 256>>>(enc);
    k_combine<<<Bsz, 256>>>(out);
}

// round 7
// speedup vs baseline: 1.5557x; 1.0081x over previous
#include <cuda_runtime.h>
#include <math.h>

#define Bsz 32
#define Ssz 2048
#define Hsz 1024
#define ECH 64                  // e-chunks for u partial sums (16 e's each)
#define WPC 8                   // warps per CTA in pass1
#define CPB 16                  // CTAs per batch element in pass1
#define SPLITS CPB              // one merged partial per CTA (CTA-level merge)
#define RPW (Ssz/(WPC*CPB))     // 16 rows per warp

// Scratch (device globals: allocation-free per harness rules)
__device__ float  g_u_part[ECH][Hsz];
__device__ float  g_u[Hsz];
__device__ float  g_scores[Bsz*Ssz];
__device__ float  g_part_m[Bsz*SPLITS];
__device__ float  g_part_l[Bsz*SPLITS];
__device__ float4 g_part_acc[(size_t)Bsz*SPLITS*(Hsz/4)];

// K0: u_part[c][h] = sum over a 16-wide e-chunk of v[e] * W[e, H+h].
__global__ void k_u(const float* __restrict__ W, const float* __restrict__ v) {
    int h  = blockIdx.x * blockDim.x + threadIdx.x;   // 0..1023
    int e0 = blockIdx.y * (Hsz/ECH);                  // 16 e's per chunk
    float s = 0.f;
    #pragma unroll
    for (int e = 0; e < Hsz/ECH; ++e)
        s = fmaf(__ldg(v + e0 + e),
                 __ldg(W + (size_t)(e0 + e)*(2*Hsz) + Hsz + h), s);
    g_u_part[blockIdx.y][h] = s;
}

// K0b: fold the 64 partials (L2-resident, 256 KB) into g_u[1024].
__global__ void k_u_reduce() {
    int h = blockIdx.x * blockDim.x + threadIdx.x;
    float s = 0.f;
    #pragma unroll
    for (int c = 0; c < ECH; ++c) s += g_u_part[c][h];
    g_u[h] = s;
}

// K1: single pass over encoder_outputs. Each warp owns RPW sequence rows of
// one batch element, processes 2 rows per iteration (16 front-batched
// LDG.128), maintains online-softmax (m, l, acc[32 regs/lane]). The 8 warps
// of a CTA then merge their partials in smem, so only ONE partial per CTA
// hits global memory (2 MB total instead of 16 MB).
__global__ void __launch_bounds__(256, 2) k_pass1(const float* __restrict__ enc) {
    __shared__ float4 su[Hsz/4];                 // 4 KB
    __shared__ float4 s_acc[WPC][Hsz/4];         // 32 KB
    __shared__ float  s_m[WPC], s_l[WPC];

    su[threadIdx.x] = ((const float4*)g_u)[threadIdx.x];
    __syncthreads();

    int b    = blockIdx.x / CPB;
    int cw   = threadIdx.x >> 5;                 // warp within CTA
    int warp = (blockIdx.x % CPB) * WPC + cw;    // global split id
    int lane = threadIdx.x & 31;
    int s0   = warp * RPW;

    const float4* base = (const float4*)enc + (size_t)(b*Ssz + s0) * (Hsz/4);

    float4 uv[8];
    #pragma unroll
    for (int j = 0; j < 8; ++j) uv[j] = su[j*32 + lane];

    float acc[32];
    #pragma unroll
    for (int i = 0; i < 32; ++i) acc[i] = 0.f;
    float m = -INFINITY, l = 0.f;

    for (int r = 0; r < RPW; r += 2) {
        const float4* rowA = base + (size_t)r * (Hsz/4);
        const float4* rowB = rowA + (Hsz/4);
        float4 xa[8], xb[8];
        #pragma unroll
        for (int j = 0; j < 8; ++j) xa[j] = rowA[j*32 + lane];
        #pragma unroll
        for (int j = 0; j < 8; ++j) xb[j] = rowB[j*32 + lane];

        float da = 0.f, db = 0.f;
        #pragma unroll
        for (int j = 0; j < 8; ++j) {
            da = fmaf(xa[j].x, uv[j].x, da);
            da = fmaf(xa[j].y, uv[j].y, da);
            da = fmaf(xa[j].z, uv[j].z, da);
            da = fmaf(xa[j].w, uv[j].w, da);
            db = fmaf(xb[j].x, uv[j].x, db);
            db = fmaf(xb[j].y, uv[j].y, db);
            db = fmaf(xb[j].z, uv[j].z, db);
            db = fmaf(xb[j].w, uv[j].w, db);
        }
        #pragma unroll
        for (int off = 16; off > 0; off >>= 1) {
            da += __shfl_xor_sync(0xffffffffu, da, off);
            db += __shfl_xor_sync(0xffffffffu, db, off);
        }

        if (lane == 0) {
            g_scores[b*Ssz + s0 + r]     = da;
            g_scores[b*Ssz + s0 + r + 1] = db;
        }

        // online softmax, row A
        if (da > m) {
            float alpha = __expf(m - da);
            l = fmaf(l, alpha, 1.f);
            #pragma unroll
            for (int j = 0; j < 8; ++j) {
                acc[4*j+0] = fmaf(acc[4*j+0], alpha, xa[j].x);
                acc[4*j+1] = fmaf(acc[4*j+1], alpha, xa[j].y);
                acc[4*j+2] = fmaf(acc[4*j+2], alpha, xa[j].z);
                acc[4*j+3] = fmaf(acc[4*j+3], alpha, xa[j].w);
            }
            m = da;
        } else {
            float p = __expf(da - m);
            l += p;
            #pragma unroll
            for (int j = 0; j < 8; ++j) {
                acc[4*j+0] = fmaf(p, xa[j].x, acc[4*j+0]);
                acc[4*j+1] = fmaf(p, xa[j].y, acc[4*j+1]);
                acc[4*j+2] = fmaf(p, xa[j].z, acc[4*j+2]);
                acc[4*j+3] = fmaf(p, xa[j].w, acc[4*j+3]);
            }
        }
        // online softmax, row B
        if (db > m) {
            float alpha = __expf(m - db);
            l = fmaf(l, alpha, 1.f);
            #pragma unroll
            for (int j = 0; j < 8; ++j) {
                acc[4*j+0] = fmaf(acc[4*j+0], alpha, xb[j].x);
                acc[4*j+1] = fmaf(acc[4*j+1], alpha, xb[j].y);
                acc[4*j+2] = fmaf(acc[4*j+2], alpha, xb[j].z);
                acc[4*j+3] = fmaf(acc[4*j+3], alpha, xb[j].w);
            }
            m = db;
        } else {
            float p = __expf(db - m);
            l += p;
            #pragma unroll
            for (int j = 0; j < 8; ++j) {
                acc[4*j+0] = fmaf(p, xb[j].x, acc[4*j+0]);
                acc[4*j+1] = fmaf(p, xb[j].y, acc[4*j+1]);
                acc[4*j+2] = fmaf(p, xb[j].z, acc[4*j+2]);
                acc[4*j+3] = fmaf(p, xb[j].w, acc[4*j+3]);
            }
        }
    }

    // --- CTA-level merge of the 8 warp partials (smem) ---
    #pragma unroll
    for (int j = 0; j < 8; ++j)
        s_acc[cw][j*32 + lane] =
            make_float4(acc[4*j], acc[4*j+1], acc[4*j+2], acc[4*j+3]);
    if (lane == 0) { s_m[cw] = m; s_l[cw] = l; }
    __syncthreads();

    // Each of the 256 threads merges one float4 column across the 8 warps.
    int t = threadIdx.x;
    float M = s_m[0];
    #pragma unroll
    for (int k = 1; k < WPC; ++k) M = fmaxf(M, s_m[k]);
    float L = 0.f;
    float4 c = make_float4(0.f, 0.f, 0.f, 0.f);
    #pragma unroll
    for (int k = 0; k < WPC; ++k) {
        float wk = __expf(s_m[k] - M);
        L = fmaf(wk, s_l[k], L);
        float4 a = s_acc[k][t];
        c.x = fmaf(wk, a.x, c.x);
        c.y = fmaf(wk, a.y, c.y);
        c.z = fmaf(wk, a.z, c.z);
        c.w = fmaf(wk, a.w, c.w);
    }

    int pidx = b*SPLITS + (blockIdx.x % CPB);
    g_part_acc[(size_t)pidx*(Hsz/4) + t] = c;
    if (t == 0) { g_part_m[pidx] = M; g_part_l[pidx] = L; }
}

// K2: per batch element, merge SPLITS(=16) CTA partials -> context
// (out[0:B*H]) and attention weights (out[B*H : B*H + B*S]).
__global__ void k_combine(float* __restrict__ out) {
    int b = blockIdx.x;
    int t = threadIdx.x;  // 256 threads; t indexes one float4 of H

    float M = -INFINITY;
    #pragma unroll
    for (int k = 0; k < SPLITS; ++k)
        M = fmaxf(M, g_part_m[b*SPLITS + k]);

    float L = 0.f;
    float4 c = make_float4(0.f, 0.f, 0.f, 0.f);
    #pragma unroll
    for (int k = 0; k < SPLITS; ++k) {
        float wk = __expf(g_part_m[b*SPLITS + k] - M);
        L = fmaf(wk, g_part_l[b*SPLITS + k], L);
        float4 a = g_part_acc[(size_t)(b*SPLITS + k)*(Hsz/4) + t];
        c.x = fmaf(wk, a.x, c.x);
        c.y = fmaf(wk, a.y, c.y);
        c.z = fmaf(wk, a.z, c.z);
        c.w = fmaf(wk, a.w, c.w);
    }
    float inv = 1.f / L;
    c.x *= inv; c.y *= inv; c.z *= inv; c.w *= inv;
    ((float4*)out)[b*(Hsz/4) + t] = c;

    // attention weights: softmax(scores) with the exact same M, L
    float* wout = out + Bsz*Hsz + b*Ssz;
    #pragma unroll
    for (int s = t; s < Ssz; s += 256)
        wout[s] = __expf(g_scores[b*Ssz + s] - M) * inv;
}

extern "C" void kernel_launch(void* const* d_in, const int* in_sizes, int n_in,
                              void* d_out, int out_size) {
    // metadata order: hidden_state, encoder_outputs, W, b, v, batch_size, seq_len
    const float* enc = (const float*)d_in[1];
    const float* W   = (const float*)d_in[2];
    const float* v   = (const float*)d_in[4];
    float* out = (float*)d_out;

    k_u<<<dim3(Hsz/128, ECH), 128>>>(W, v);
    k_u_reduce<<<Hsz/128, 128>>>();
    k_pass1<<<Bsz*CPB, 256>>>(enc);
    k_combine<<<Bsz, 256>>>(out);
}

// round 8
// speedup vs baseline: 1.5950x; 1.0253x over previous
#include <cuda_runtime.h>
#include <math.h>

#define Bsz 32
#define Ssz 2048
#define Hsz 1024
#define ECH 64                  // e-chunks for u partial sums (16 e's each)
#define WPC 8                   // warps per CTA in pass1
#define CPB 16                  // CTAs per batch element in pass1
#define SPLITS CPB              // one merged partial per CTA (CTA-level merge)
#define RPW (Ssz/(WPC*CPB))     // 16 rows per warp

// Scratch (device globals: allocation-free per harness rules)
__device__ float  g_u_part[ECH][Hsz];
__device__ float  g_u[Hsz];
__device__ float  g_scores[Bsz*Ssz];
__device__ float  g_part_m[Bsz*SPLITS];
__device__ float  g_part_l[Bsz*SPLITS];
__device__ float4 g_part_acc[(size_t)Bsz*SPLITS*(Hsz/4)];

// K0: u_part[c][h] = sum over a 16-wide e-chunk of v[e] * W[e, H+h].
__global__ void k_u(const float* __restrict__ W, const float* __restrict__ v) {
    int h  = blockIdx.x * blockDim.x + threadIdx.x;   // 0..1023
    int e0 = blockIdx.y * (Hsz/ECH);                  // 16 e's per chunk
    float s = 0.f;
    #pragma unroll
    for (int e = 0; e < Hsz/ECH; ++e)
        s = fmaf(__ldg(v + e0 + e),
                 __ldg(W + (size_t)(e0 + e)*(2*Hsz) + Hsz + h), s);
    g_u_part[blockIdx.y][h] = s;
}

// K0b: fold the 64 partials (L2-resident, 256 KB) into g_u[1024].
__global__ void k_u_reduce() {
    int h = blockIdx.x * blockDim.x + threadIdx.x;
    float s = 0.f;
    #pragma unroll
    for (int c = 0; c < ECH; ++c) s += g_u_part[c][h];
    g_u[h] = s;
}

// K1: single pass over encoder_outputs. Each warp owns RPW sequence rows of
// one batch element, processes 2 rows per iteration (16 front-batched
// LDG.128), maintains online-softmax (m, l, acc[32 regs/lane]). The 8 warps
// of a CTA then merge their partials in smem, so only ONE partial per CTA
// hits global memory (2 MB total instead of 16 MB).
__global__ void __launch_bounds__(256, 2) k_pass1(const float* __restrict__ enc) {
    __shared__ float4 su[Hsz/4];                 // 4 KB
    __shared__ float4 s_acc[WPC][Hsz/4];         // 32 KB
    __shared__ float  s_m[WPC], s_l[WPC];

    su[threadIdx.x] = ((const float4*)g_u)[threadIdx.x];
    __syncthreads();

    int b    = blockIdx.x / CPB;
    int cw   = threadIdx.x >> 5;                 // warp within CTA
    int warp = (blockIdx.x % CPB) * WPC + cw;    // global split id
    int lane = threadIdx.x & 31;
    int s0   = warp * RPW;

    const float4* base = (const float4*)enc + (size_t)(b*Ssz + s0) * (Hsz/4);

    float4 uv[8];
    #pragma unroll
    for (int j = 0; j < 8; ++j) uv[j] = su[j*32 + lane];

    float acc[32];
    #pragma unroll
    for (int i = 0; i < 32; ++i) acc[i] = 0.f;
    float m = -INFINITY, l = 0.f;

    for (int r = 0; r < RPW; r += 2) {
        const float4* rowA = base + (size_t)r * (Hsz/4);
        const float4* rowB = rowA + (Hsz/4);
        float4 xa[8], xb[8];
        #pragma unroll
        for (int j = 0; j < 8; ++j) xa[j] = rowA[j*32 + lane];
        #pragma unroll
        for (int j = 0; j < 8; ++j) xb[j] = rowB[j*32 + lane];

        float da = 0.f, db = 0.f;
        #pragma unroll
        for (int j = 0; j < 8; ++j) {
            da = fmaf(xa[j].x, uv[j].x, da);
            da = fmaf(xa[j].y, uv[j].y, da);
            da = fmaf(xa[j].z, uv[j].z, da);
            da = fmaf(xa[j].w, uv[j].w, da);
            db = fmaf(xb[j].x, uv[j].x, db);
            db = fmaf(xb[j].y, uv[j].y, db);
            db = fmaf(xb[j].z, uv[j].z, db);
            db = fmaf(xb[j].w, uv[j].w, db);
        }
        #pragma unroll
        for (int off = 16; off > 0; off >>= 1) {
            da += __shfl_xor_sync(0xffffffffu, da, off);
            db += __shfl_xor_sync(0xffffffffu, db, off);
        }

        if (lane == 0) {
            g_scores[b*Ssz + s0 + r]     = da;
            g_scores[b*Ssz + s0 + r + 1] = db;
        }

        // online softmax, row A
        if (da > m) {
            float alpha = __expf(m - da);
            l = fmaf(l, alpha, 1.f);
            #pragma unroll
            for (int j = 0; j < 8; ++j) {
                acc[4*j+0] = fmaf(acc[4*j+0], alpha, xa[j].x);
                acc[4*j+1] = fmaf(acc[4*j+1], alpha, xa[j].y);
                acc[4*j+2] = fmaf(acc[4*j+2], alpha, xa[j].z);
                acc[4*j+3] = fmaf(acc[4*j+3], alpha, xa[j].w);
            }
            m = da;
        } else {
            float p = __expf(da - m);
            l += p;
            #pragma unroll
            for (int j = 0; j < 8; ++j) {
                acc[4*j+0] = fmaf(p, xa[j].x, acc[4*j+0]);
                acc[4*j+1] = fmaf(p, xa[j].y, acc[4*j+1]);
                acc[4*j+2] = fmaf(p, xa[j].z, acc[4*j+2]);
                acc[4*j+3] = fmaf(p, xa[j].w, acc[4*j+3]);
            }
        }
        // online softmax, row B
        if (db > m) {
            float alpha = __expf(m - db);
            l = fmaf(l, alpha, 1.f);
            #pragma unroll
            for (int j = 0; j < 8; ++j) {
                acc[4*j+0] = fmaf(acc[4*j+0], alpha, xb[j].x);
                acc[4*j+1] = fmaf(acc[4*j+1], alpha, xb[j].y);
                acc[4*j+2] = fmaf(acc[4*j+2], alpha, xb[j].z);
                acc[4*j+3] = fmaf(acc[4*j+3], alpha, xb[j].w);
            }
            m = db;
        } else {
            float p = __expf(db - m);
            l += p;
            #pragma unroll
            for (int j = 0; j < 8; ++j) {
                acc[4*j+0] = fmaf(p, xb[j].x, acc[4*j+0]);
                acc[4*j+1] = fmaf(p, xb[j].y, acc[4*j+1]);
                acc[4*j+2] = fmaf(p, xb[j].z, acc[4*j+2]);
                acc[4*j+3] = fmaf(p, xb[j].w, acc[4*j+3]);
            }
        }
    }

    // --- CTA-level merge of the 8 warp partials (smem) ---
    #pragma unroll
    for (int j = 0; j < 8; ++j)
        s_acc[cw][j*32 + lane] =
            make_float4(acc[4*j], acc[4*j+1], acc[4*j+2], acc[4*j+3]);
    if (lane == 0) { s_m[cw] = m; s_l[cw] = l; }
    __syncthreads();

    // Each of the 256 threads merges one float4 column across the 8 warps.
    int t = threadIdx.x;
    float M = s_m[0];
    #pragma unroll
    for (int k = 1; k < WPC; ++k) M = fmaxf(M, s_m[k]);
    float L = 0.f;
    float4 c = make_float4(0.f, 0.f, 0.f, 0.f);
    #pragma unroll
    for (int k = 0; k < WPC; ++k) {
        float wk = __expf(s_m[k] - M);
        L = fmaf(wk, s_l[k], L);
        float4 a = s_acc[k][t];
        c.x = fmaf(wk, a.x, c.x);
        c.y = fmaf(wk, a.y, c.y);
        c.z = fmaf(wk, a.z, c.z);
        c.w = fmaf(wk, a.w, c.w);
    }

    int pidx = b*SPLITS + (blockIdx.x % CPB);
    g_part_acc[(size_t)pidx*(Hsz/4) + t] = c;
    if (t == 0) { g_part_m[pidx] = M; g_part_l[pidx] = L; }
}

// K2: per batch element, merge SPLITS(=16) CTA partials -> context
// (out[0:B*H]) and attention weights (out[B*H : B*H + B*S]).
__global__ void k_combine(float* __restrict__ out) {
    int b = blockIdx.x;
    int t = threadIdx.x;  // 256 threads; t indexes one float4 of H

    float M = -INFINITY;
    #pragma unroll
    for (int k = 0; k < SPLITS; ++k)
        M = fmaxf(M, g_part_m[b*SPLITS + k]);

    float L = 0.f;
    float4 c = make_float4(0.f, 0.f, 0.f, 0.f);
    #pragma unroll
    for (int k = 0; k < SPLITS; ++k) {
        float wk = __expf(g_part_m[b*SPLITS + k] - M);
        L = fmaf(wk, g_part_l[b*SPLITS + k], L);
        float4 a = g_part_acc[(size_t)(b*SPLITS + k)*(Hsz/4) + t];
        c.x = fmaf(wk, a.x, c.x);
        c.y = fmaf(wk, a.y, c.y);
        c.z = fmaf(wk, a.z, c.z);
        c.w = fmaf(wk, a.w, c.w);
    }
    float inv = 1.f / L;
    c.x *= inv; c.y *= inv; c.z *= inv; c.w *= inv;
    ((float4*)out)[b*(Hsz/4) + t] = c;

    // attention weights: softmax(scores) with the exact same M, L
    float* wout = out + Bsz*Hsz + b*Ssz;
    #pragma unroll
    for (int s = t; s < Ssz; s += 256)
        wout[s] = __expf(g_scores[b*Ssz + s] - M) * inv;
}

extern "C" void kernel_launch(void* const* d_in, const int* in_sizes, int n_in,
                              void* d_out, int out_size) {
    // metadata order: hidden_state, encoder_outputs, W, b, v, batch_size, seq_len
    const float* enc = (const float*)d_in[1];
    const float* W   = (const float*)d_in[2];
    const float* v   = (const float*)d_in[4];
    float* out = (float*)d_out;

    k_u<<<dim3(Hsz/128, ECH), 128>>>(W, v);
    k_u_reduce<<<Hsz/128, 128>>>();
    k_pass1<<<Bsz*CPB, 256>>>(enc);
    k_combine<<<Bsz, 256>>>(out);
}